// round 9
// baseline (speedup 1.0000x reference)
#include <cuda_runtime.h>

#define CROP 512
#define GRID_N 8
#define NBINS 256
#define TILE 64        // CROP / GRID_N
#define SRC_W 640
#define SRC_H 640
#define NB 64          // batch
#define NWARP 8        // warps per block
#define NTILES (NB * GRID_N * GRID_N)   // 4096

// LUT scratch (values pre-divided by 255): 4 MB
__device__ float g_luts[NB * GRID_N * GRID_N * NBINS];
// packed bins scratch: 4096 tiles * 4 words * 256 threads * 4B = 16.7 MB
__device__ unsigned g_binsw[NTILES * 4 * NBINS];
// monotonic global-barrier counters (NEVER reset; replay-safe)
__device__ unsigned g_bcnt, g_bgen;

__device__ __forceinline__ float ldcg_f(const float* p) {
    float v;
    asm volatile("ld.global.cg.f32 %0, [%1];" : "=f"(v) : "l"(p));
    return v;
}

// ---------------------------------------------------------------------------
// Persistent fused kernel (single wave, one global barrier).
// Phase A (grid-stride over tiles):
//   copy tile : stream 64x64 output tile (flip-folded addressing).
//   clahe tile: read in output order, shared-atomic histogram, retain bins
//               packed 4/word -> scan -> LUT publish -> bins to scratch.
// Global barrier (monotonic generation counter; all blocks resident).
// Phase B (same grid-stride): clahe tiles only — stage 4 quadrant float4
//   tables in smem, reload own packed bins, bilinear apply, store.
// ---------------------------------------------------------------------------
__global__ void __launch_bounds__(256)
clahe_persistent_kernel(const float* __restrict__ x,
                        const int* __restrict__ hflip,
                        const int* __restrict__ vflip,
                        const int* __restrict__ offy,
                        const int* __restrict__ offx,
                        const int* __restrict__ apply_clahe,
                        float* __restrict__ out) {
    const int t = threadIdx.x;            // 0..255
    const int G = gridDim.x;

    __shared__ __align__(16) unsigned char smem_raw[16 * NBINS * 4];  // 16 KB
    __shared__ float wsum[NWARP];

    const int j  = t & 63;                // tile-local column
    const int i0 = t >> 6;                // tile-local row 0..3
    const int w    = t >> 5;
    const int lane = t & 31;

    // ================= Phase A =================
    for (int tid = blockIdx.x; tid < NTILES; tid += G) {
        const int b    = tid >> 6;
        const int tile = tid & 63;
        const int ty   = tile >> 3;
        const int tx   = tile & 7;

        const int   hf = hflip[b];
        const int   vf = vflip[b];
        const int   oy = offy[b];
        const int   ox = offx[b];
        const float* xb = x + (size_t)b * (SRC_W * SRC_H);

        const int gj  = tx * TILE + j;
        const int gi0 = ty * TILE + i0;

        const int rs      = vf ? -SRC_W : SRC_W;
        const int rowbase = vf ? (SRC_H - 1 - oy) : oy;
        const int sw      = hf ? (SRC_W - 1 - ox - gj) : (ox + gj);
        const float* p    = xb + rowbase * SRC_W + sw + gi0 * rs;
        const int pstep   = 4 * rs;

        if (!apply_clahe[b]) {
            // ---- copy tile (overlaps clahe atomics with DRAM streaming) ----
            float* q = out + ((size_t)b << 18) + (gi0 << 9) + gj;
            #pragma unroll
            for (int k = 0; k < 16; k++) {
                __stcs(q, __ldg(p));
                p += pstep; q += (4 << 9);
            }
            continue;
        }

        // ---- clahe tile: histogram + LUT ----
        int (*hist)[NBINS] = (int (*)[NBINS])smem_raw;

        __syncthreads();                   // guard smem reuse across iterations
        #pragma unroll
        for (int k = 0; k < NWARP; k++) hist[k][t] = 0;
        __syncthreads();

        unsigned packed[4] = {0u, 0u, 0u, 0u};
        #pragma unroll
        for (int k = 0; k < 16; k++) {
            float v = __ldg(p);
            p += pstep;
            int bin = (int)(v * (float)NBINS);     // v in [0,1) -> 0..255
            atomicAdd(&hist[w][bin], 1);
            packed[k >> 2] |= (unsigned)bin << ((k & 3) * 8);
        }
        __syncthreads();

        int hsum = 0;
        #pragma unroll
        for (int k = 0; k < NWARP; k++) hsum += hist[k][t];
        float clipped = fminf((float)hsum, 12.8f);  // 0.8*4096/256

        // inclusive 256-thread scan (shuffle + 2 barriers)
        float v = clipped;
        #pragma unroll
        for (int s = 1; s < 32; s <<= 1) {
            float n = __shfl_up_sync(0xffffffffu, v, s);
            if (lane >= s) v += n;
        }
        if (lane == 31) wsum[w] = v;
        __syncthreads();
        if (w == 0 && lane < NWARP) {
            float ws = wsum[lane];
            #pragma unroll
            for (int s = 1; s < NWARP; s <<= 1) {
                float n = __shfl_up_sync(0xffu, ws, s);
                if (lane >= s) ws += n;
            }
            wsum[lane] = ws;
        }
        __syncthreads();

        float cum    = v + ((w > 0) ? wsum[w - 1] : 0.0f);
        float excess = 4096.0f - wsum[NWARP - 1];

        float lut = (cum + excess * (float)(t + 1) * (1.0f / 256.0f)) * (1.0f / 4096.0f);
        lut = fminf(fmaxf(lut, 0.0f), 1.0f);
        g_luts[((size_t)tid << 8) + t] = lut;       // (b*64+tile)*256 + t

        // bins scratch (same thread re-reads in phase B -> L1/L2-hot)
        unsigned* bw = g_binsw + ((size_t)tid << 10) + t;
        bw[0]       = packed[0];
        bw[NBINS]   = packed[1];
        bw[2*NBINS] = packed[2];
        bw[3*NBINS] = packed[3];
    }

    // ================= global barrier (monotonic, replay-safe) =============
    __syncthreads();
    if (t == 0) {
        __threadfence();                   // publish LUT stores
        unsigned my = atomicAdd(&g_bcnt, 1u);
        unsigned target = my / (unsigned)G + 1u;
        if (my % (unsigned)G == (unsigned)G - 1u)
            atomicAdd(&g_bgen, 1u);        // last arriver releases the wave
        while (*(volatile unsigned*)&g_bgen < target)
            __nanosleep(128);
        __threadfence();                   // acquire peers' LUT stores
    }
    __syncthreads();

    // ================= Phase B =================
    float4* T = (float4*)smem_raw;         // T[quadrant*256 + bin]
    for (int tid = blockIdx.x; tid < NTILES; tid += G) {
        const int b = tid >> 6;
        if (!apply_clahe[b]) continue;
        const int tile = tid & 63;
        const int ty   = tile >> 3;
        const int tx   = tile & 7;

        __syncthreads();                   // prev tile's table readers done
        {
            const int ya0 = max(ty - 1, 0), ya1 = ty;
            const int yb1 = min(ty + 1, GRID_N - 1);
            const int xa0 = max(tx - 1, 0), xa1 = tx;
            const int xb1 = min(tx + 1, GRID_N - 1);
            const float* lb = g_luts + ((size_t)b << 14);
            #define LUTQ(yy, xx) ldcg_f(lb + (((yy) * GRID_N + (xx)) << 8) + t)
            T[0 * NBINS + t] = make_float4(LUTQ(ya0, xa0), LUTQ(ya0, xa1), LUTQ(ya1, xa0), LUTQ(ya1, xa1));
            T[1 * NBINS + t] = make_float4(LUTQ(ya0, xa1), LUTQ(ya0, xb1), LUTQ(ya1, xa1), LUTQ(ya1, xb1));
            T[2 * NBINS + t] = make_float4(LUTQ(ya1, xa0), LUTQ(ya1, xa1), LUTQ(yb1, xa0), LUTQ(yb1, xa1));
            T[3 * NBINS + t] = make_float4(LUTQ(ya1, xa1), LUTQ(ya1, xb1), LUTQ(yb1, xa1), LUTQ(yb1, xb1));
            #undef LUTQ
        }
        __syncthreads();

        const unsigned* bw = g_binsw + ((size_t)tid << 10) + t;
        unsigned packed[4];
        packed[0] = bw[0];
        packed[1] = bw[NBINS];
        packed[2] = bw[2*NBINS];
        packed[3] = bw[3*NBINS];

        const int gj  = tx * TILE + j;
        const int gi0 = ty * TILE + i0;
        float* q = out + ((size_t)b << 18) + (gi0 << 9) + gj;

        const int qx = j >> 5;
        const float fx = (qx ? ((float)j - 31.5f) : ((float)j + 32.5f)) * (1.0f / TILE);
        const float4* Ta = T + qx * NBINS;          // rows i < 32 (qy=0)
        const float4* Tb = T + (2 + qx) * NBINS;    // rows i >= 32 (qy=1)

        float fy = ((float)i0 + 32.5f) * (1.0f / TILE);
        #pragma unroll
        for (int k = 0; k < 8; k++) {
            int bin = (packed[k >> 2] >> ((k & 3) * 8)) & 255;
            float4 tt = Ta[bin];
            float top = fmaf(fx, tt.y - tt.x, tt.x);
            float bot = fmaf(fx, tt.w - tt.z, tt.z);
            __stcs(q, fmaf(fy, bot - top, top));
            q += (4 << 9); fy += (4.0f / TILE);
        }
        fy = ((float)i0 + 0.5f) * (1.0f / TILE);
        #pragma unroll
        for (int k = 8; k < 16; k++) {
            int bin = (packed[k >> 2] >> ((k & 3) * 8)) & 255;
            float4 tt = Tb[bin];
            float top = fmaf(fx, tt.y - tt.x, tt.x);
            float bot = fmaf(fx, tt.w - tt.z, tt.z);
            __stcs(q, fmaf(fy, bot - top, top));
            q += (4 << 9); fy += (4.0f / TILE);
        }
    }
}

extern "C" void kernel_launch(void* const* d_in, const int* in_sizes, int n_in,
                              void* d_out, int out_size) {
    const float* x          = (const float*)d_in[0];
    const int*   hflip      = (const int*)d_in[1];
    const int*   vflip      = (const int*)d_in[2];
    const int*   offy       = (const int*)d_in[3];
    const int*   offx       = (const int*)d_in[4];
    const int*   apply_clahe= (const int*)d_in[5];
    float*       out        = (float*)d_out;

    // single-wave grid: resident capacity, computed fresh each call
    // (host-side queries; deterministic; capture-safe)
    int sms = 0, nb = 0;
    cudaDeviceGetAttribute(&sms, cudaDevAttrMultiProcessorCount, 0);
    cudaOccupancyMaxActiveBlocksPerMultiprocessor(
        &nb, clahe_persistent_kernel, NBINS, 0);
    int grid = sms * nb;
    if (grid > NTILES) grid = NTILES;
    if (grid < 1) grid = 1;

    clahe_persistent_kernel<<<grid, NBINS>>>(
        x, hflip, vflip, offy, offx, apply_clahe, out);
}

// round 10
// speedup vs baseline: 1.1162x; 1.1162x over previous
#include <cuda_runtime.h>

#define CROP 512
#define GRID_N 8
#define NBINS 256
#define TILE 64        // CROP / GRID_N
#define SRC_W 640
#define SRC_H 640
#define NB 64          // batch
#define NWARP 8        // warps per block

// LUT scratch (values pre-divided by 255): 64 * 64 tiles * 256 bins * 4B = 4 MB
__device__ float g_luts[NB * GRID_N * GRID_N * NBINS];
// monotonic arrival / generation counters (NEVER reset; replay-safe)
__device__ unsigned g_cnt[NB];
__device__ unsigned g_gen[NB];

__device__ __forceinline__ float ldcg_f(const float* p) {
    float v;
    asm volatile("ld.global.cg.f32 %0, [%1];" : "=f"(v) : "l"(p));
    return v;
}

// ---------------------------------------------------------------------------
// Fused kernel: one block per (batch, tile).
//  copy batch : stream the 64x64 output tile (flip-folded addressing).
//  clahe batch: read tile in OUTPUT order (4-deep batched streaming loads),
//               shared-atomic histogram + retain bins packed in regs ->
//               clip/redistribute/scan -> publish LUT -> per-batch
//               generation-counter barrier -> stage 4 quadrant float4 tables
//               (9 LUT loads, composed in regs) -> apply from retained bins.
// ---------------------------------------------------------------------------
__global__ void __launch_bounds__(256)
clahe_fused_kernel(const float* __restrict__ x,
                   const int* __restrict__ hflip,
                   const int* __restrict__ vflip,
                   const int* __restrict__ offy,
                   const int* __restrict__ offx,
                   const int* __restrict__ apply_clahe,
                   float* __restrict__ out) {
    const int b    = blockIdx.x >> 6;
    const int tile = blockIdx.x & 63;
    const int ty   = tile >> 3;
    const int tx   = tile & 7;
    const int t    = threadIdx.x;         // 0..255

    const int   hf = hflip[b];
    const int   vf = vflip[b];
    const int   oy = offy[b];
    const int   ox = offx[b];
    const float* xb = x + (size_t)b * (SRC_W * SRC_H);

    // per-thread output-tile mapping: column j, rows i0+4k (k=0..15)
    const int j   = t & 63;
    const int i0  = t >> 6;
    const int gj  = tx * TILE + j;
    const int gi0 = ty * TILE + i0;

    // flip-folded source addressing
    const int rs      = vf ? -SRC_W : SRC_W;
    const int rowbase = vf ? (SRC_H - 1 - oy) : oy;
    const int sw      = hf ? (SRC_W - 1 - ox - gj) : (ox + gj);
    const float* p    = xb + rowbase * SRC_W + sw + gi0 * rs;
    const int pstep   = 4 * rs;

    float* q0 = out + ((size_t)b << 18) + (gi0 << 9) + gj;
    const int qstep = 4 << 9;

    if (!apply_clahe[b]) {
        // ---------------- copy path ----------------
        float* q = q0;
        #pragma unroll
        for (int r = 0; r < 4; r++) {
            float v0 = __ldcs(p);
            float v1 = __ldcs(p + pstep);
            float v2 = __ldcs(p + 2 * pstep);
            float v3 = __ldcs(p + 3 * pstep);
            p += 4 * pstep;
            __stcs(q,             v0);
            __stcs(q + qstep,     v1);
            __stcs(q + 2 * qstep, v2);
            __stcs(q + 3 * qstep, v3);
            q += 4 * qstep;
        }
        return;
    }

    // ---------------- clahe path ----------------
    __shared__ __align__(16) unsigned char smem_raw[4 * NBINS * 16];  // 16 KB
    __shared__ float wsum[NWARP];

    int (*hist)[NBINS] = (int (*)[NBINS])smem_raw;
    const int w    = t >> 5;
    const int lane = t & 31;

    #pragma unroll
    for (int k = 0; k < NWARP; k++) hist[k][t] = 0;
    __syncthreads();

    // read (output order, 4-deep batched), histogram, retain packed bins
    unsigned packed[4];
    #pragma unroll
    for (int r = 0; r < 4; r++) {
        float v0 = __ldcs(p);
        float v1 = __ldcs(p + pstep);
        float v2 = __ldcs(p + 2 * pstep);
        float v3 = __ldcs(p + 3 * pstep);
        p += 4 * pstep;
        int b0 = (int)(v0 * (float)NBINS);      // v in [0,1) -> 0..255
        int b1 = (int)(v1 * (float)NBINS);
        int b2 = (int)(v2 * (float)NBINS);
        int b3 = (int)(v3 * (float)NBINS);
        atomicAdd(&hist[w][b0], 1);
        atomicAdd(&hist[w][b1], 1);
        atomicAdd(&hist[w][b2], 1);
        atomicAdd(&hist[w][b3], 1);
        packed[r] = (unsigned)b0 | ((unsigned)b1 << 8)
                  | ((unsigned)b2 << 16) | ((unsigned)b3 << 24);
    }
    __syncthreads();

    // fold per-warp histograms; clip at 0.8*4096/256 = 12.8
    int hsum = 0;
    #pragma unroll
    for (int k = 0; k < NWARP; k++) hsum += hist[k][t];
    float clipped = fminf((float)hsum, 12.8f);

    // inclusive 256-thread scan (shuffle + 2 barriers)
    float v = clipped;
    #pragma unroll
    for (int s = 1; s < 32; s <<= 1) {
        float n = __shfl_up_sync(0xffffffffu, v, s);
        if (lane >= s) v += n;
    }
    if (lane == 31) wsum[w] = v;
    __syncthreads();
    if (w == 0 && lane < NWARP) {
        float ws = wsum[lane];
        #pragma unroll
        for (int s = 1; s < NWARP; s <<= 1) {
            float n = __shfl_up_sync(0xffu, ws, s);
            if (lane >= s) ws += n;
        }
        wsum[lane] = ws;
    }
    __syncthreads();

    float cum    = v + ((w > 0) ? wsum[w - 1] : 0.0f);
    float excess = 4096.0f - wsum[NWARP - 1];

    // lut = clip(cumsum(clipped + excess/256)/4096, 0, 1)
    float lut = (cum + excess * (float)(t + 1) * (1.0f / 256.0f)) * (1.0f / 4096.0f);
    lut = fminf(fmaxf(lut, 0.0f), 1.0f);
    g_luts[(((size_t)blockIdx.x) << 8) + t] = lut;

    // ---- per-batch generation barrier (monotonic, replay-safe) ----
    __syncthreads();                       // all LUT stores issued block-wide
    if (t == 0) {
        __threadfence();                   // publish this block's LUT stores
        unsigned my = atomicAdd(&g_cnt[b], 1u);
        unsigned target = (my >> 6) + 1u;  // this replay's cohort generation
        if ((my & 63u) == 63u)
            atomicAdd(&g_gen[b], 1u);      // 64th arriver releases the cohort
        while (*(volatile unsigned*)&g_gen[b] < target)
            __nanosleep(64);
        __threadfence();                   // acquire peers' LUT stores
    }
    __syncthreads();

    // stage 4 quadrant tables from 9 LUT loads (overwrites hist region)
    float4* T = (float4*)smem_raw;        // T[quadrant*256 + bin]
    {
        const int ya0 = max(ty - 1, 0), ya1 = ty, yb1 = min(ty + 1, GRID_N - 1);
        const int xa0 = max(tx - 1, 0), xa1 = tx, xb1 = min(tx + 1, GRID_N - 1);
        const float* lb = g_luts + ((size_t)b << 14);
        float l00 = ldcg_f(lb + ((ya0 * GRID_N + xa0) << 8) + t);
        float l01 = ldcg_f(lb + ((ya0 * GRID_N + xa1) << 8) + t);
        float l02 = ldcg_f(lb + ((ya0 * GRID_N + xb1) << 8) + t);
        float l10 = ldcg_f(lb + ((ya1 * GRID_N + xa0) << 8) + t);
        float l11 = ldcg_f(lb + ((ya1 * GRID_N + xa1) << 8) + t);
        float l12 = ldcg_f(lb + ((ya1 * GRID_N + xb1) << 8) + t);
        float l20 = ldcg_f(lb + ((yb1 * GRID_N + xa0) << 8) + t);
        float l21 = ldcg_f(lb + ((yb1 * GRID_N + xa1) << 8) + t);
        float l22 = ldcg_f(lb + ((yb1 * GRID_N + xb1) << 8) + t);
        T[0 * NBINS + t] = make_float4(l00, l01, l10, l11);   // qy=0, qx=0
        T[1 * NBINS + t] = make_float4(l01, l02, l11, l12);   // qy=0, qx=1
        T[2 * NBINS + t] = make_float4(l10, l11, l20, l21);   // qy=1, qx=0
        T[3 * NBINS + t] = make_float4(l11, l12, l21, l22);   // qy=1, qx=1
    }
    __syncthreads();

    // apply from retained bins (no input re-read)
    const int qx = j >> 5;
    const float fx = (qx ? ((float)j - 31.5f) : ((float)j + 32.5f)) * (1.0f / TILE);

    const float4* Ta = T + qx * NBINS;          // rows i < 32 (qy=0)
    const float4* Tb = T + (2 + qx) * NBINS;    // rows i >= 32 (qy=1)

    float* q = q0;
    float fy = ((float)i0 + 32.5f) * (1.0f / TILE);   // exact dyadic
    #pragma unroll
    for (int k = 0; k < 8; k++) {
        int bin = (packed[k >> 2] >> ((k & 3) * 8)) & 255;
        float4 tt = Ta[bin];
        float top = fmaf(fx, tt.y - tt.x, tt.x);
        float bot = fmaf(fx, tt.w - tt.z, tt.z);
        __stcs(q, fmaf(fy, bot - top, top));
        q += qstep; fy += (4.0f / TILE);
    }
    fy = ((float)i0 + 0.5f) * (1.0f / TILE);
    #pragma unroll
    for (int k = 8; k < 16; k++) {
        int bin = (packed[k >> 2] >> ((k & 3) * 8)) & 255;
        float4 tt = Tb[bin];
        float top = fmaf(fx, tt.y - tt.x, tt.x);
        float bot = fmaf(fx, tt.w - tt.z, tt.z);
        __stcs(q, fmaf(fy, bot - top, top));
        q += qstep; fy += (4.0f / TILE);
    }
}

extern "C" void kernel_launch(void* const* d_in, const int* in_sizes, int n_in,
                              void* d_out, int out_size) {
    const float* x          = (const float*)d_in[0];
    const int*   hflip      = (const int*)d_in[1];
    const int*   vflip      = (const int*)d_in[2];
    const int*   offy       = (const int*)d_in[3];
    const int*   offx       = (const int*)d_in[4];
    const int*   apply_clahe= (const int*)d_in[5];
    float*       out        = (float*)d_out;

    clahe_fused_kernel<<<NB * GRID_N * GRID_N, NBINS>>>(
        x, hflip, vflip, offy, offx, apply_clahe, out);
}

// round 13
// speedup vs baseline: 1.2962x; 1.1612x over previous
#include <cuda_runtime.h>

#define CROP 512
#define GRID_N 8
#define NBINS 256
#define TILE 64        // CROP / GRID_N
#define SRC_W 640
#define SRC_H 640
#define NB 64          // batch
#define NWARP 8        // warps per block

// LUT scratch (values pre-divided by 255): 64 * 64 tiles * 256 bins * 4B = 4 MB
__device__ float g_luts[NB * GRID_N * GRID_N * NBINS];
// monotonic arrival / generation counters (NEVER reset; replay-safe)
__device__ unsigned g_cnt[NB];
__device__ unsigned g_gen[NB];

__device__ __forceinline__ float ldcg_f(const float* p) {
    float v;
    asm volatile("ld.global.cg.f32 %0, [%1];" : "=f"(v) : "l"(p));
    return v;
}

// ---------------------------------------------------------------------------
// Fused kernel: one block per (batch, tile). regs capped for 8 blocks/SM.
//  copy batch : stream the 64x64 output tile (flip-folded addressing).
//  clahe batch: read tile in OUTPUT order (two interleaved 8-chains for MLP),
//               shared-atomic histogram + retain bins packed in regs ->
//               clip/redistribute/scan -> publish LUT -> per-batch
//               generation barrier -> stage 4 quadrant float4 tables from
//               9 LUT vectors (own LUT from register) -> apply, store.
// ---------------------------------------------------------------------------
__global__ void __launch_bounds__(256, 8)
clahe_fused_kernel(const float* __restrict__ x,
                   const int* __restrict__ hflip,
                   const int* __restrict__ vflip,
                   const int* __restrict__ offy,
                   const int* __restrict__ offx,
                   const int* __restrict__ apply_clahe,
                   float* __restrict__ out) {
    const int b    = blockIdx.x >> 6;
    const int tile = blockIdx.x & 63;
    const int ty   = tile >> 3;
    const int tx   = tile & 7;
    const int t    = threadIdx.x;         // 0..255

    const int   hf = hflip[b];
    const int   vf = vflip[b];
    const int   oy = offy[b];
    const int   ox = offx[b];
    const float* xb = x + (size_t)b * (SRC_W * SRC_H);

    // per-thread output-tile mapping: column j, rows i0+4k (k=0..15)
    const int j   = t & 63;
    const int i0  = t >> 6;
    const int gj  = tx * TILE + j;
    const int gi0 = ty * TILE + i0;

    // flip-folded source addressing
    const int rs      = vf ? -SRC_W : SRC_W;
    const int rowbase = vf ? (SRC_H - 1 - oy) : oy;
    const int sw      = hf ? (SRC_W - 1 - ox - gj) : (ox + gj);
    const float* p    = xb + rowbase * SRC_W + sw + gi0 * rs;
    const int pstep   = 4 * rs;

    float* q0 = out + ((size_t)b << 18) + (gi0 << 9) + gj;
    const int qstep = 4 << 9;

    if (!apply_clahe[b]) {
        // ---------------- copy path ----------------
        float* q = q0;
        #pragma unroll
        for (int k = 0; k < 16; k++) {
            __stcs(q, __ldg(p));
            p += pstep; q += qstep;
        }
        return;
    }

    // ---------------- clahe path ----------------
    __shared__ __align__(16) unsigned char smem_raw[4 * NBINS * 16];  // 16 KB
    __shared__ float wsum[NWARP];

    int (*hist)[NBINS] = (int (*)[NBINS])smem_raw;
    const int w    = t >> 5;
    const int lane = t & 31;

    #pragma unroll
    for (int k = 0; k < NWARP; k++) hist[k][t] = 0;
    __syncthreads();

    // read (output order), histogram, retain bins packed as bytes.
    // Two interleaved 8-chains double memory parallelism at ~2 extra regs.
    unsigned packed[4] = {0u, 0u, 0u, 0u};
    {
        const float* pA = p;
        const float* pB = p + 8 * pstep;
        #pragma unroll
        for (int k = 0; k < 8; k++) {
            float vA = __ldg(pA); pA += pstep;
            float vB = __ldg(pB); pB += pstep;
            int bA = (int)(vA * (float)NBINS);     // v in [0,1) -> 0..255
            int bB = (int)(vB * (float)NBINS);
            atomicAdd(&hist[w][bA], 1);
            atomicAdd(&hist[w][bB], 1);
            packed[k >> 2]       |= (unsigned)bA << ((k & 3) * 8);
            packed[2 + (k >> 2)] |= (unsigned)bB << ((k & 3) * 8);
        }
    }
    __syncthreads();

    // fold per-warp histograms; clip at 0.8*4096/256 = 12.8
    int hsum = 0;
    #pragma unroll
    for (int k = 0; k < NWARP; k++) hsum += hist[k][t];
    float clipped = fminf((float)hsum, 12.8f);

    // inclusive 256-thread scan (shuffle + 2 barriers)
    float v = clipped;
    #pragma unroll
    for (int s = 1; s < 32; s <<= 1) {
        float n = __shfl_up_sync(0xffffffffu, v, s);
        if (lane >= s) v += n;
    }
    if (lane == 31) wsum[w] = v;
    __syncthreads();
    if (w == 0 && lane < NWARP) {
        float ws = wsum[lane];
        #pragma unroll
        for (int s = 1; s < NWARP; s <<= 1) {
            float n = __shfl_up_sync(0xffu, ws, s);
            if (lane >= s) ws += n;
        }
        wsum[lane] = ws;
    }
    __syncthreads();

    float cum    = v + ((w > 0) ? wsum[w - 1] : 0.0f);
    float excess = 4096.0f - wsum[NWARP - 1];

    // lut = clip(cumsum(clipped + excess/256)/4096, 0, 1)
    float lut = (cum + excess * (float)(t + 1) * (1.0f / 256.0f)) * (1.0f / 4096.0f);
    lut = fminf(fmaxf(lut, 0.0f), 1.0f);
    g_luts[(((size_t)blockIdx.x) << 8) + t] = lut;

    // ---- per-batch generation barrier (monotonic, replay-safe) ----
    __syncthreads();                       // all LUT stores issued block-wide
    if (t == 0) {
        __threadfence();                   // publish this block's LUT stores
        unsigned my = atomicAdd(&g_cnt[b], 1u);
        unsigned target = (my >> 6) + 1u;  // this replay's cohort generation
        if ((my & 63u) == 63u)
            atomicAdd(&g_gen[b], 1u);      // 64th arriver releases the cohort
        while (*(volatile unsigned*)&g_gen[b] < target)
            __nanosleep(64);
        __threadfence();                   // acquire peers' LUT stores
    }
    __syncthreads();

    // stage 4 quadrant tables from 9 LUT vectors (own LUT from register)
    float4* T = (float4*)smem_raw;        // T[quadrant*256 + bin]
    {
        const int ya0 = max(ty - 1, 0), ya1 = ty, yb1 = min(ty + 1, GRID_N - 1);
        const int xa0 = max(tx - 1, 0), xa1 = tx, xb1 = min(tx + 1, GRID_N - 1);
        const float* lb = g_luts + ((size_t)b << 14);
        float l00 = ldcg_f(lb + ((ya0 * GRID_N + xa0) << 8) + t);
        float l01 = ldcg_f(lb + ((ya0 * GRID_N + xa1) << 8) + t);
        float l02 = ldcg_f(lb + ((ya0 * GRID_N + xb1) << 8) + t);
        float l10 = ldcg_f(lb + ((ya1 * GRID_N + xa0) << 8) + t);
        float l11 = lut;                   // this tile's own LUT
        float l12 = ldcg_f(lb + ((ya1 * GRID_N + xb1) << 8) + t);
        float l20 = ldcg_f(lb + ((yb1 * GRID_N + xa0) << 8) + t);
        float l21 = ldcg_f(lb + ((yb1 * GRID_N + xa1) << 8) + t);
        float l22 = ldcg_f(lb + ((yb1 * GRID_N + xb1) << 8) + t);
        T[0 * NBINS + t] = make_float4(l00, l01, l10, l11);   // qy=0, qx=0
        T[1 * NBINS + t] = make_float4(l01, l02, l11, l12);   // qy=0, qx=1
        T[2 * NBINS + t] = make_float4(l10, l11, l20, l21);   // qy=1, qx=0
        T[3 * NBINS + t] = make_float4(l11, l12, l21, l22);   // qy=1, qx=1
    }
    __syncthreads();

    // apply from retained bins (no input re-read)
    const int qx = j >> 5;
    const float fx = (qx ? ((float)j - 31.5f) : ((float)j + 32.5f)) * (1.0f / TILE);

    const float4* Ta = T + qx * NBINS;          // rows i < 32 (qy=0)
    const float4* Tb = T + (2 + qx) * NBINS;    // rows i >= 32 (qy=1)

    float* q = q0;
    float fy = ((float)i0 + 32.5f) * (1.0f / TILE);   // exact dyadic
    #pragma unroll
    for (int k = 0; k < 8; k++) {
        int bin = (packed[k >> 2] >> ((k & 3) * 8)) & 255;
        float4 tt = Ta[bin];
        float top = fmaf(fx, tt.y - tt.x, tt.x);
        float bot = fmaf(fx, tt.w - tt.z, tt.z);
        __stcs(q, fmaf(fy, bot - top, top));
        q += qstep; fy += (4.0f / TILE);
    }
    fy = ((float)i0 + 0.5f) * (1.0f / TILE);
    #pragma unroll
    for (int k = 8; k < 16; k++) {
        int bin = (packed[k >> 2] >> ((k & 3) * 8)) & 255;
        float4 tt = Tb[bin];
        float top = fmaf(fx, tt.y - tt.x, tt.x);
        float bot = fmaf(fx, tt.w - tt.z, tt.z);
        __stcs(q, fmaf(fy, bot - top, top));
        q += qstep; fy += (4.0f / TILE);
    }
}

extern "C" void kernel_launch(void* const* d_in, const int* in_sizes, int n_in,
                              void* d_out, int out_size) {
    const float* x          = (const float*)d_in[0];
    const int*   hflip      = (const int*)d_in[1];
    const int*   vflip      = (const int*)d_in[2];
    const int*   offy       = (const int*)d_in[3];
    const int*   offx       = (const int*)d_in[4];
    const int*   apply_clahe= (const int*)d_in[5];
    float*       out        = (float*)d_out;

    clahe_fused_kernel<<<NB * GRID_N * GRID_N, NBINS>>>(
        x, hflip, vflip, offy, offx, apply_clahe, out);
}